// round 12
// baseline (speedup 1.0000x reference)
#include <cuda_runtime.h>

// out = cumprod_j( cos(w_j) * cos(x @ W_pre^T + b_pre) ) @ W_post^T + b_post
//
// Analytic reduction of the quantum layer:
//   z_j   = cos(q_weights_j) * cos(angle_j)
//   <Z_i> = prod_{j<=i} z_j            (CNOT chain = prefix-XOR)
//
// Block = (row pair, column QUARTER): grid=512 x 256 thr -> 3-4 blocks/SM
// (launch_bounds(256,4), 64-reg budget). Smaller, more numerous blocks give
// finer-grained stall coverage and cheaper 8-warp barriers. Each warp owns
// 2 qubits x 2 rows (4 accumulators) in phase 1 -> more FFMA per LDG.

#define NQ   16
#define DIN  1024
#define DOUT 1024

__global__ __launch_bounds__(256, 4)
void quantum_projector_kernel(const float* __restrict__ x,
                              const float* __restrict__ W_pre,
                              const float* __restrict__ b_pre,
                              const float* __restrict__ q_weights,
                              const float* __restrict__ W_post,
                              const float* __restrict__ b_post,
                              float* __restrict__ out)
{
    __shared__ float4 sx0[DIN / 4];      // 4 KB: row r0
    __shared__ float4 sx1[DIN / 4];      // 4 KB: row r1
    __shared__ float  s_angle[2 * NQ];   // [row][qubit]
    __shared__ float4 s_wz[8][8];        // warp-private scan slots (8 warps)

    const int bx      = blockIdx.x;
    const int pair    = bx >> 2;         // 128 row pairs
    const int quarter = bx & 3;          // 4 column quarters of 256
    const int r0      = pair * 2;
    const int r1      = r0 + 1;
    const int tid     = threadIdx.x;
    const int warp    = tid >> 5;        // 8 warps
    const int lane    = tid & 31;

    // ---- Stage both x rows into smem (256 threads, two float4 each) ----
    {
        const float4* __restrict__ x4 = reinterpret_cast<const float4*>(x);
        sx0[tid] = x4[r0 * (DIN / 4) + tid];
        sx1[tid] = x4[r1 * (DIN / 4) + tid];
    }

    // ---- Prefetch this thread's W_post column (shared by both rows) ----
    const int col = quarter * 256 + tid;
    const float4* __restrict__ Wp4 = reinterpret_cast<const float4*>(W_post);
    float4 wreg[4];
#pragma unroll
    for (int i = 0; i < 4; i++)
        wreg[i] = Wp4[col * 4 + i];
    const float bp = b_post[col];

    __syncthreads();   // barrier 1: x staged (8-warp domain)

    // ---- Phase 1: warp w -> qubits q0=2w, q1=2w+1, both rows ----
    {
        const int q0 = warp * 2;
        const int q1 = q0 + 1;
        const float4* __restrict__ wa4 = reinterpret_cast<const float4*>(W_pre + q0 * DIN);
        const float4* __restrict__ wb4 = reinterpret_cast<const float4*>(W_pre + q1 * DIN);

        float a00 = 0.f, a01 = 0.f, a10 = 0.f, a11 = 0.f;   // [row][qubit]
#pragma unroll
        for (int i = 0; i < 8; i++) {
            const int k = lane + 32 * i;
            const float4 wa = wa4[k];
            const float4 wb = wb4[k];
            const float4 x0 = sx0[k];
            const float4 x1 = sx1[k];
            a00 += x0.x * wa.x + x0.y * wa.y + x0.z * wa.z + x0.w * wa.w;
            a01 += x0.x * wb.x + x0.y * wb.y + x0.z * wb.z + x0.w * wb.w;
            a10 += x1.x * wa.x + x1.y * wa.y + x1.z * wa.z + x1.w * wa.w;
            a11 += x1.x * wb.x + x1.y * wb.y + x1.z * wb.z + x1.w * wb.w;
        }
#pragma unroll
        for (int off = 16; off >= 1; off >>= 1) {
            a00 += __shfl_xor_sync(0xffffffffu, a00, off);
            a01 += __shfl_xor_sync(0xffffffffu, a01, off);
            a10 += __shfl_xor_sync(0xffffffffu, a10, off);
            a11 += __shfl_xor_sync(0xffffffffu, a11, off);
        }
        if (lane == 0) {
            const float b0 = b_pre[q0];
            const float b1 = b_pre[q1];
            s_angle[q0]      = a00 + b0;
            s_angle[q1]      = a01 + b1;
            s_angle[NQ + q0] = a10 + b0;
            s_angle[NQ + q1] = a11 + b1;
        }
    }
    __syncthreads();   // barrier 2: angles ready

    // ---- Phase 2: EVERY warp computes the dual-row prefix scan ----
    // lanes 0..15 -> row0, lanes 16..31 -> row1 (segmented shfl_up scan),
    // broadcast within the warp via its private smem slot.
    {
        const int q   = lane & 15;
        const int seg = lane >> 4;
        float v = __cosf(q_weights[q]) * __cosf(s_angle[seg * NQ + q]);
#pragma unroll
        for (int off = 1; off <= 8; off <<= 1) {
            float t = __shfl_up_sync(0xffffffffu, v, off);
            if (q >= off) v *= t;   // segment boundary: q < off blocks carry-in
        }
        reinterpret_cast<float*>(s_wz[warp])[lane] = v;
        __syncwarp();
    }

    // ---- Phase 3: one column x 2 rows per thread; zq via broadcast LDS.128 ----
    float d0 = bp, d1 = bp;
#pragma unroll
    for (int i = 0; i < 4; i++) {
        const float4 za = s_wz[warp][i];       // row0 qubits 4i..4i+3
        const float4 zb = s_wz[warp][4 + i];   // row1
        const float4 w  = wreg[i];
        d0 += za.x * w.x + za.y * w.y + za.z * w.z + za.w * w.w;
        d1 += zb.x * w.x + zb.y * w.y + zb.z * w.z + zb.w * w.w;
    }

    out[r0 * DOUT + col] = d0;
    out[r1 * DOUT + col] = d1;
}

extern "C" void kernel_launch(void* const* d_in, const int* in_sizes, int n_in,
                              void* d_out, int out_size)
{
    const float* x         = (const float*)d_in[0];   // [256, 1024]
    const float* W_pre     = (const float*)d_in[1];   // [16, 1024]
    const float* b_pre     = (const float*)d_in[2];   // [16]
    const float* q_weights = (const float*)d_in[3];   // [16]
    const float* W_post    = (const float*)d_in[4];   // [1024, 16]
    const float* b_post    = (const float*)d_in[5];   // [1024]
    float* out             = (float*)d_out;           // [256, 1024]

    quantum_projector_kernel<<<512, 256>>>(x, W_pre, b_pre, q_weights,
                                           W_post, b_post, out);
}

// round 13
// speedup vs baseline: 1.2043x; 1.2043x over previous
#include <cuda_runtime.h>

// out = cumprod_j( cos(w_j) * cos(x @ W_pre^T + b_pre) ) @ W_post^T + b_post
//
// Analytic reduction of the quantum layer:
//   z_j   = cos(q_weights_j) * cos(angle_j)
//   <Z_i> = prod_{j<=i} z_j            (CNOT chain = prefix-XOR)
//
// Block = (row pair, column half): grid=256 x 512 thr, 2 blocks/SM.
// ONE block barrier total:
//   - x read directly via LDG (L1-resident after first toucher) -> no smem
//     stage, no barrier-1 rendezvous; each warp's mainloop starts immediately
//   - dual-row warp reduction in 6 shuffles (xor16 fold, then per-half xor8..1)
//   - per-warp redundant segmented prefix scan + __syncwarp broadcast
//   - W_post column register-cached, reused across the 2 rows

#define NQ   16
#define DIN  1024
#define DOUT 1024
#define B    256

__global__ __launch_bounds__(512, 2)
void quantum_projector_kernel(const float* __restrict__ x,
                              const float* __restrict__ W_pre,
                              const float* __restrict__ b_pre,
                              const float* __restrict__ q_weights,
                              const float* __restrict__ W_post,
                              const float* __restrict__ b_post,
                              float* __restrict__ out)
{
    __shared__ float  s_angle[2 * NQ];   // [row][qubit]
    __shared__ float4 s_wz[16][8];       // warp-private scan slots

    const int bx   = blockIdx.x;
    const int pair = bx >> 1;            // which row pair
    const int half = bx & 1;             // which 512-column half
    const int r0   = pair * 2;
    const int r1   = r0 + 1;
    const int tid  = threadIdx.x;
    const int warp = tid >> 5;           // 16 warps = 16 qubits
    const int lane = tid & 31;

    // ---- Prefetch this thread's W_post column (shared by both rows) ----
    const int col = half * 512 + tid;
    const float4* __restrict__ Wp4 = reinterpret_cast<const float4*>(W_post);
    float4 wreg[4];
#pragma unroll
    for (int i = 0; i < 4; i++)
        wreg[i] = Wp4[col * 4 + i];
    const float bp = b_post[col];

    // ---- Phase 1: both rows' angle[warp]; all operands via LDG ----
    // x rows hit L1 after the first warp touches them; W_pre rows are
    // per-warp exclusive. No staging barrier: each warp only waits on its
    // own scoreboard, iteration-pipelined.
    {
        const float4* __restrict__ w4  = reinterpret_cast<const float4*>(W_pre + warp * DIN);
        const float4* __restrict__ x04 = reinterpret_cast<const float4*>(x + r0 * DIN);
        const float4* __restrict__ x14 = reinterpret_cast<const float4*>(x + r1 * DIN);

        float a0e = 0.f, a0o = 0.f, a1e = 0.f, a1o = 0.f;
#pragma unroll
        for (int i = 0; i < 4; i++) {
            const int ke = lane + 64 * i;
            const int ko = ke + 32;
            const float4 we  = w4[ke],  wo  = w4[ko];
            const float4 xe0 = x04[ke], xo0 = x04[ko];
            const float4 xe1 = x14[ke], xo1 = x14[ko];
            a0e += xe0.x * we.x + xe0.y * we.y + xe0.z * we.z + xe0.w * we.w;
            a0o += xo0.x * wo.x + xo0.y * wo.y + xo0.z * wo.z + xo0.w * wo.w;
            a1e += xe1.x * we.x + xe1.y * we.y + xe1.z * we.z + xe1.w * we.w;
            a1o += xo1.x * wo.x + xo1.y * wo.y + xo1.z * wo.z + xo1.w * wo.w;
        }
        float acc0 = a0e + a0o;
        float acc1 = a1e + a1o;

        // Dual-row reduction in 6 shuffles:
        // fold halves for both rows, then each 16-lane half reduces one row.
        acc0 += __shfl_xor_sync(0xffffffffu, acc0, 16);
        acc1 += __shfl_xor_sync(0xffffffffu, acc1, 16);
        float v = (lane < 16) ? acc0 : acc1;
#pragma unroll
        for (int off = 8; off >= 1; off >>= 1)
            v += __shfl_xor_sync(0xffffffffu, v, off);

        if (lane == 0)  s_angle[warp]      = v + b_pre[warp];   // row 0
        if (lane == 16) s_angle[NQ + warp] = v + b_pre[warp];   // row 1
    }
    __syncthreads();   // the ONLY block barrier: angles ready

    // ---- Phase 2: EVERY warp computes the dual-row prefix scan ----
    // lanes 0..15 -> row0, lanes 16..31 -> row1 (segmented shfl_up scan),
    // broadcast within the warp via its private smem slot.
    {
        const int q   = lane & 15;
        const int seg = lane >> 4;
        float v = __cosf(q_weights[q]) * __cosf(s_angle[seg * NQ + q]);
#pragma unroll
        for (int off = 1; off <= 8; off <<= 1) {
            float t = __shfl_up_sync(0xffffffffu, v, off);
            if (q >= off) v *= t;   // segment boundary: q < off blocks carry-in
        }
        reinterpret_cast<float*>(s_wz[warp])[lane] = v;
        __syncwarp();
    }

    // ---- Phase 3: one column x 2 rows per thread; zq via broadcast LDS.128 ----
    float d0 = bp, d1 = bp;
#pragma unroll
    for (int i = 0; i < 4; i++) {
        const float4 za = s_wz[warp][i];       // row0 qubits 4i..4i+3
        const float4 zb = s_wz[warp][4 + i];   // row1
        const float4 w  = wreg[i];
        d0 += za.x * w.x + za.y * w.y + za.z * w.z + za.w * w.w;
        d1 += zb.x * w.x + zb.y * w.y + zb.z * w.z + zb.w * w.w;
    }

    out[r0 * DOUT + col] = d0;
    out[r1 * DOUT + col] = d1;
}

extern "C" void kernel_launch(void* const* d_in, const int* in_sizes, int n_in,
                              void* d_out, int out_size)
{
    const float* x         = (const float*)d_in[0];   // [256, 1024]
    const float* W_pre     = (const float*)d_in[1];   // [16, 1024]
    const float* b_pre     = (const float*)d_in[2];   // [16]
    const float* q_weights = (const float*)d_in[3];   // [16]
    const float* W_post    = (const float*)d_in[4];   // [1024, 16]
    const float* b_post    = (const float*)d_in[5];   // [1024]
    float* out             = (float*)d_out;           // [256, 1024]

    quantum_projector_kernel<<<B, 512>>>(x, W_pre, b_pre, q_weights,
                                         W_post, b_post, out);
}